// round 1
// baseline (speedup 1.0000x reference)
#include <cuda_runtime.h>

// Problem constants (fixed by setup_inputs)
#define BB      48
#define NKC     800
#define NMBON   20
#define NFBN    60
#define NDAN    20
#define NREC    100
#define TT      121
#define NSTEP   120
#define W_MAXC  0.05f

#define NTHREADS 512

// scratch: r_kc transposed to [B, T, NKC]
__device__ float g_rkcT[(long)BB * TT * NKC];

// ---------------------------------------------------------------------------
// Transpose r_kc [B, NKC, T] -> g_rkcT [B, T, NKC]
// ---------------------------------------------------------------------------
__global__ void transpose_kernel(const float* __restrict__ rkc) {
    __shared__ float tile[32][33];
    const int bz = blockIdx.z;          // batch
    const int kt = blockIdx.y;          // k tile (0..24)
    const int tt = blockIdx.x;          // t tile (0..3)
    const int tx = threadIdx.x, ty = threadIdx.y;

    int k = kt * 32 + ty;
    int t = tt * 32 + tx;
    if (t < TT)
        tile[ty][tx] = rkc[((long)bz * NKC + k) * TT + t];
    __syncthreads();
    int t2 = tt * 32 + ty;
    int k2 = kt * 32 + tx;
    if (t2 < TT)
        g_rkcT[((long)bz * TT + t2) * NKC + k2] = tile[tx][ty];
}

// ---------------------------------------------------------------------------
// Main RNN kernel: one CTA per batch element. 512 threads.
//   group g = tid>>8 (2 groups), chunk q = tid&255 (active q<200, k = 4q)
//   thread owns W[m][4q..4q+3], wt[...] for m = 10*g .. 10*g+9 in registers.
// ---------------------------------------------------------------------------
// shared layout (floats):
//  WrT 10000 | rkc 800 | rbkc 800 | r 200 | bias 100 | ifbn 60
//  red 64*20=1280 | rdan 20 | rbdan 20 | wro 20 | wext 120
#define SM_FLOATS (10000 + 800 + 800 + 200 + 100 + 60 + 1280 + 20 + 20 + 20 + 120)

__global__ __launch_bounds__(NTHREADS, 1) void rnn_kernel(
    const float* __restrict__ r_ext,     // [B, 2, T]
    const float* __restrict__ time_arr,  // [T]
    const float* __restrict__ W_kc0,     // [B, 20, 800]
    const float* __restrict__ wt0,       // [B, 20, 800]
    const float* __restrict__ W_recur,   // [100, 100]
    const float* __restrict__ W_readout, // [1, 20]
    const float* __restrict__ bias,      // [100]
    const float* __restrict__ W_ext,     // [60, 2]
    float* __restrict__ out)
{
    extern __shared__ float sm[];
    float* WrT     = sm;                  // 10000
    float* rkc_s   = WrT + 10000;         // 800 (16B aligned: 40000B)
    float* rbkc_s  = rkc_s + 800;         // 800
    float* r_s     = rbkc_s + 800;        // 200 (double buffer of 100)
    float* bias_s  = r_s + 200;           // 100
    float* ifbn_s  = bias_s + 100;        // 60
    float* red_s   = ifbn_s + 60;         // 64*20 (layout [slot][m])
    float* rdan_s  = red_s + 1280;        // 20
    float* rbdan_s = rdan_s + 20;         // 20
    float* wro_s   = rbdan_s + 20;        // 20
    float* wext_s  = wro_s + 20;          // 120

    const int tid  = threadIdx.x;
    const int b    = blockIdx.x;
    const int lane = tid & 31;
    const int warp = tid >> 5;
    const int g    = tid >> 8;            // 0 or 1
    const int q    = tid & 255;           // chunk id
    const int wig  = warp & 7;            // warp within group
    const bool act = (q < 200);
    const int m_base = g * 10;

    float* out_r  = out;
    float* out_W  = out + (long)TT * BB * NREC;
    float* out_wt = out_W + (long)TT * BB * NMBON * NKC;
    float* out_ro = out_wt + (long)TT * BB * NMBON * NKC;

    const float dt  = time_arr[1] - time_arr[0];
    const float a_r = dt;                 // dt / TAU_R, TAU_R = 1
    const float a_w = dt * 0.2f;          // dt / TAU_W, TAU_W = 5

    // ---------------- init ----------------
    for (int idx = tid; idx < NREC * NREC; idx += NTHREADS) {
        int i = idx / NREC, j = idx % NREC;
        float v = W_recur[idx];
        if (i < NMBON && j >= NREC - NDAN) v = 0.f;   // Wr[:n_mbon, -n_dan:] = 0
        WrT[j * NREC + i] = v;
    }
    if (tid < NREC)     bias_s[tid] = bias[tid];
    if (tid < NMBON)    wro_s[tid]  = W_readout[tid];
    if (tid < NFBN * 2) wext_s[tid] = W_ext[tid];
    if (tid < NREC) {
        float r0 = (tid < NMBON) ? 0.f : 0.1f;
        r_s[tid] = r0;                                    // buffer 0 (t even)
        out_r[(long)b * NREC + tid] = r0;                 // r_all[0]
    }
    if (tid < NDAN) rbdan_s[tid] = 0.1f;                  // r0 dan section
    for (int k = tid; k < NKC; k += NTHREADS)
        rbkc_s[k] = g_rkcT[(long)b * TT * NKC + k];       // rb_kc0 = r_kc[:,:,0]
    if (tid == 0) out_ro[b] = 0.f;                        // readout0 = 0

    float4 Wv[10], wtv[10];
    if (act) {
        const long ibase = ((long)b * NMBON) * NKC + q * 4;
        const long obase = ((long)b) * (NMBON * NKC) + q * 4;  // t=0 slice
#pragma unroll
        for (int mm = 0; mm < 10; ++mm) {
            const int m = m_base + mm;
            float4 w  = *(const float4*)(W_kc0 + ibase + (long)m * NKC);
            float4 wt = *(const float4*)(wt0   + ibase + (long)m * NKC);
            Wv[mm] = w; wtv[mm] = wt;
            *(float4*)(out_W  + obase + (long)m * NKC) = w;
            *(float4*)(out_wt + obase + (long)m * NKC) = wt;
        }
    } else {
#pragma unroll
        for (int mm = 0; mm < 10; ++mm) {
            Wv[mm]  = make_float4(0.f, 0.f, 0.f, 0.f);
            wtv[mm] = make_float4(0.f, 0.f, 0.f, 0.f);
        }
    }
    __syncthreads();

    // ---------------- time loop ----------------
    for (int t = 0; t < NSTEP; ++t) {
        // Phase A: stage rkc_t, update rb_kc, compute I_fbn
        if (tid < 200) {
            float4 kc = *(const float4*)(&g_rkcT[((long)b * TT + t) * NKC] + tid * 4);
            *(float4*)(rkc_s + tid * 4) = kc;
            float4 bk = *(const float4*)(rbkc_s + tid * 4);
            bk.x = fmaf(a_w, kc.x - bk.x, bk.x);
            bk.y = fmaf(a_w, kc.y - bk.y, bk.y);
            bk.z = fmaf(a_w, kc.z - bk.z, bk.z);
            bk.w = fmaf(a_w, kc.w - bk.w, bk.w);
            *(float4*)(rbkc_s + tid * 4) = bk;
        } else if (tid < 200 + NFBN) {
            int f = tid - 200;
            float e0 = r_ext[((long)b * 2 + 0) * TT + t];
            float e1 = r_ext[((long)b * 2 + 1) * TT + t];
            ifbn_s[f] = wext_s[f * 2] * e0 + wext_s[f * 2 + 1] * e1;
        }
        __syncthreads();

        // Phase B: I_mbon partial sums (per-warp, 2 shuffle rounds)
        {
            float4 kc = make_float4(0.f, 0.f, 0.f, 0.f);
            if (act) kc = *(const float4*)(rkc_s + q * 4);
#pragma unroll
            for (int mm = 0; mm < 10; ++mm) {
                float4 w = Wv[mm];
                float p = w.x * kc.x + w.y * kc.y + w.z * kc.z + w.w * kc.w;
                p += __shfl_xor_sync(0xffffffffu, p, 16);
                p += __shfl_xor_sync(0xffffffffu, p, 8);
                if (lane < 8)
                    red_s[(wig * 8 + lane) * NMBON + (m_base + mm)] = p;
            }
        }
        __syncthreads();

        // Phase C: recurrent update (threads 0..99)
        const float* rc = r_s + (t & 1) * NREC;
        float* rn_buf   = r_s + ((t + 1) & 1) * NREC;
        if (tid < NREC) {
            const int i = tid;
            float itot;
            if (i < NMBON) {
                float s0 = 0.f, s1 = 0.f, s2 = 0.f, s3 = 0.f;
#pragma unroll
                for (int k = 0; k < 64; k += 4) {
                    s0 += red_s[(k + 0) * NMBON + i];
                    s1 += red_s[(k + 1) * NMBON + i];
                    s2 += red_s[(k + 2) * NMBON + i];
                    s3 += red_s[(k + 3) * NMBON + i];
                }
                itot = (s0 + s1) + (s2 + s3);
            } else if (i < NMBON + NFBN) {
                itot = ifbn_s[i - NMBON];
            } else {
                itot = 0.f;
            }
            float a0 = 0.f, a1 = 0.f, a2 = 0.f, a3 = 0.f;
#pragma unroll
            for (int j = 0; j < NREC; j += 4) {
                a0 = fmaf(rc[j + 0], WrT[(j + 0) * NREC + i], a0);
                a1 = fmaf(rc[j + 1], WrT[(j + 1) * NREC + i], a1);
                a2 = fmaf(rc[j + 2], WrT[(j + 2) * NREC + i], a2);
                a3 = fmaf(rc[j + 3], WrT[(j + 3) * NREC + i], a3);
            }
            float pre  = ((a0 + a1) + (a2 + a3)) + bias_s[i] + itot;
            float relu = fmaxf(pre, 0.f);
            float rold = rc[i];
            float rn   = fmaf(a_r, relu - rold, rold);
            rn_buf[i] = rn;
            out_r[((long)(t + 1) * BB + b) * NREC + i] = rn;
            if (i >= NREC - NDAN) {
                int m = i - (NREC - NDAN);
                rdan_s[m] = rn;
                float rb = rbdan_s[m];
                rbdan_s[m] = fmaf(a_w, rn - rb, rb);
            }
        }
        __syncthreads();

        // Phase D: plasticity update + streaming stores
        if (act) {
            float4 kc = *(const float4*)(rkc_s + q * 4);
            float4 bk = *(const float4*)(rbkc_s + q * 4);
            const long obase = ((long)(t + 1) * BB + b) * (NMBON * NKC) + q * 4;
#pragma unroll
            for (int mm = 0; mm < 10; ++mm) {
                const int m = m_base + mm;
                const float rbd = rbdan_s[m];
                const float rd  = rdan_s[m];
                float4 w = Wv[mm], wt = wtv[mm];
                float dw;
                dw = fmaf(rbd, kc.x, -(rd * bk.x)); wt.x = fmaf(dw, dt, wt.x);
                dw = fmaf(rbd, kc.y, -(rd * bk.y)); wt.y = fmaf(dw, dt, wt.y);
                dw = fmaf(rbd, kc.z, -(rd * bk.z)); wt.z = fmaf(dw, dt, wt.z);
                dw = fmaf(rbd, kc.w, -(rd * bk.w)); wt.w = fmaf(dw, dt, wt.w);
                w.x = fminf(fmaxf(fmaf(a_w, wt.x - w.x, w.x), 0.f), W_MAXC);
                w.y = fminf(fmaxf(fmaf(a_w, wt.y - w.y, w.y), 0.f), W_MAXC);
                w.z = fminf(fmaxf(fmaf(a_w, wt.z - w.z, w.z), 0.f), W_MAXC);
                w.w = fminf(fmaxf(fmaf(a_w, wt.w - w.w, w.w), 0.f), W_MAXC);
                Wv[mm] = w; wtv[mm] = wt;
                *(float4*)(out_W  + obase + (long)m * NKC) = w;
                *(float4*)(out_wt + obase + (long)m * NKC) = wt;
            }
        }
        if (warp == 0) {   // readout
            float v = (lane < NMBON) ? rn_buf[lane] * wro_s[lane] : 0.f;
            v += __shfl_xor_sync(0xffffffffu, v, 16);
            v += __shfl_xor_sync(0xffffffffu, v, 8);
            v += __shfl_xor_sync(0xffffffffu, v, 4);
            v += __shfl_xor_sync(0xffffffffu, v, 2);
            v += __shfl_xor_sync(0xffffffffu, v, 1);
            if (lane == 0) out_ro[(long)(t + 1) * BB + b] = v;
        }
        __syncthreads();   // protect rkc_s/rbkc_s for next Phase A
    }
}

// ---------------------------------------------------------------------------
extern "C" void kernel_launch(void* const* d_in, const int* in_sizes, int n_in,
                              void* d_out, int out_size) {
    const float* r_kc      = (const float*)d_in[0];
    const float* r_ext     = (const float*)d_in[1];
    const float* time_arr  = (const float*)d_in[2];
    const float* W_kc0     = (const float*)d_in[3];
    const float* wt0       = (const float*)d_in[4];
    const float* W_recur   = (const float*)d_in[5];
    const float* W_readout = (const float*)d_in[6];
    const float* bias      = (const float*)d_in[7];
    const float* W_ext     = (const float*)d_in[8];
    float* out = (float*)d_out;

    cudaFuncSetAttribute(rnn_kernel, cudaFuncAttributeMaxDynamicSharedMemorySize,
                         SM_FLOATS * (int)sizeof(float));

    transpose_kernel<<<dim3(4, 25, BB), dim3(32, 32)>>>(r_kc);
    rnn_kernel<<<BB, NTHREADS, SM_FLOATS * (int)sizeof(float)>>>(
        r_ext, time_arr, W_kc0, wt0, W_recur, W_readout, bias, W_ext, out);
}

// round 3
// speedup vs baseline: 1.1638x; 1.1638x over previous
#include <cuda_runtime.h>
#include <cstdint>

// Problem constants (fixed by setup_inputs)
#define BB      48
#define NKC     800
#define NMBON   20
#define NFBN    60
#define NDAN    20
#define NREC    100
#define TT      121
#define NSTEP   120
#define W_MAXC  0.05f

#define NTHREADS 512

// scratch: r_kc transposed to [B, T, NKC]
__device__ float g_rkcT[(long)BB * TT * NKC];

// ---------------------------------------------------------------------------
// Transpose r_kc [B, NKC, T] -> g_rkcT [B, T, NKC]
// ---------------------------------------------------------------------------
__global__ void transpose_kernel(const float* __restrict__ rkc) {
    __shared__ float tile[32][33];
    const int bz = blockIdx.z;          // batch
    const int kt = blockIdx.y;          // k tile (0..24)
    const int tt = blockIdx.x;          // t tile (0..3)
    const int tx = threadIdx.x, ty = threadIdx.y;

    int k = kt * 32 + ty;
    int t = tt * 32 + tx;
    if (t < TT)
        tile[ty][tx] = rkc[((long)bz * NKC + k) * TT + t];
    __syncthreads();
    int t2 = tt * 32 + ty;
    int k2 = kt * 32 + tx;
    if (t2 < TT)
        g_rkcT[((long)bz * TT + t2) * NKC + k2] = tile[tx][ty];
}

// ---------------------------------------------------------------------------
// Main RNN kernel: one CTA per batch element. 512 threads.
//   group g = tid>>8 (2 groups), chunk q = tid&255 (active q<200, k = 4q)
//   thread owns W[m][4q..4q+3], wt[...] for m = 10*g .. 10*g+9 in registers.
// Pipeline: 2 barriers/step; rkc prefetched 1 step ahead via cp.async into a
// triple-buffered smem ring by the 112 non-owner "staging" threads.
// IMPORTANT: Phase B (full-mask shuffles) is executed by ALL threads — mixed
// act/stage warps (6, 14) would deadlock otherwise.
// ---------------------------------------------------------------------------
// shared layout (floats):
//  WrT 10000 | rkc3 2400 | rbkc2 1600 | r 200 | bias 100 | ifbn 128
//  red 32*20=640 | rdan 20 | rbdan 20 | wro 20 | wext 120
#define SM_FLOATS (10000 + 2400 + 1600 + 200 + 100 + 128 + 640 + 20 + 20 + 20 + 120)

__global__ __launch_bounds__(NTHREADS, 1) void rnn_kernel(
    const float* __restrict__ r_ext,     // [B, 2, T]
    const float* __restrict__ time_arr,  // [T]
    const float* __restrict__ W_kc0,     // [B, 20, 800]
    const float* __restrict__ wt0,       // [B, 20, 800]
    const float* __restrict__ W_recur,   // [100, 100]
    const float* __restrict__ W_readout, // [1, 20]
    const float* __restrict__ bias,      // [100]
    const float* __restrict__ W_ext,     // [60, 2]
    float* __restrict__ out)
{
    extern __shared__ float sm[];
    float* WrT     = sm;                  // 10000
    float* rkc3    = WrT + 10000;         // 3 x 800 (ring)
    float* rbkc    = rkc3 + 2400;         // 2 x 800 (double buffer)
    float* r_s     = rbkc + 1600;         // 2 x 100
    float* bias_s  = r_s + 200;           // 100
    float* ifbn    = bias_s + 100;        // 2 x 64
    float* red_s   = ifbn + 128;          // 32 x 20  [slot][m]
    float* rdan_s  = red_s + 640;         // 20
    float* rbdan_s = rdan_s + 20;         // 20
    float* wro_s   = rbdan_s + 20;        // 20
    float* wext_s  = wro_s + 20;          // 120

    const int tid  = threadIdx.x;
    const int b    = blockIdx.x;
    const int lane = tid & 31;
    const int warp = tid >> 5;
    const int g    = tid >> 8;            // 0 or 1
    const int q    = tid & 255;           // chunk id
    const int wig  = warp & 7;            // warp within group
    const bool act = (q < 200);
    const int m_base = g * 10;

    // staging threads: the 112 non-owner threads (q in 200..255)
    const bool is_stage = !act;
    const int  s = (tid < 256) ? (tid - 200) : (tid - 400);  // 0..111 (stage only)
    const int  c1 = s;                    // rkc float4 chunk 1
    const int  c2 = s + 112;              // rkc float4 chunk 2 (valid if s<88)

    float* out_r  = out;
    float* out_W  = out + (long)TT * BB * NREC;
    float* out_wt = out_W + (long)TT * BB * NMBON * NKC;
    float* out_ro = out_wt + (long)TT * BB * NMBON * NKC;

    const float dt  = time_arr[1] - time_arr[0];
    const float a_r = dt;                 // dt / TAU_R, TAU_R = 1
    const float a_w = dt * 0.2f;          // dt / TAU_W, TAU_W = 5

    const float* rkc_g = g_rkcT + (long)b * TT * NKC;

    // ---------------- init ----------------
    for (int idx = tid; idx < NREC * NREC; idx += NTHREADS) {
        int i = idx / NREC, j = idx % NREC;
        float v = W_recur[idx];
        if (i < NMBON && j >= NREC - NDAN) v = 0.f;   // Wr[:n_mbon, -n_dan:] = 0
        WrT[j * NREC + i] = v;
    }
    if (tid < NREC)     bias_s[tid] = bias[tid];
    if (tid < NMBON)    wro_s[tid]  = W_readout[tid];
    if (tid < NFBN * 2) wext_s[tid] = W_ext[tid];
    if (tid < NREC) {
        float r0 = (tid < NMBON) ? 0.f : 0.1f;
        r_s[tid] = r0;                                    // buffer 0 (t=0 reads buf 0)
        out_r[(long)b * NREC + tid] = r0;                 // r_all[0]
    }
    if (tid < NDAN) rbdan_s[tid] = 0.1f;                  // r0 dan section
    // rkc ring buf0 = rkc(0); rbkc buf1 = rb_kc0 = rkc(0)
    for (int k = tid; k < NKC; k += NTHREADS) {
        float v = rkc_g[k];
        rkc3[k] = v;
        rbkc[800 + k] = v;
    }
    // ifbn buf0 from r_ext(.,0)
    if (tid < NFBN) {
        float e0 = r_ext[((long)b * 2 + 0) * TT];
        float e1 = r_ext[((long)b * 2 + 1) * TT];
        ifbn[tid] = wext_s[tid * 2] * e0 + wext_s[tid * 2 + 1] * e1;
    }
    if (tid == 0) out_ro[b] = 0.f;                        // readout0 = 0

    float4 Wv[10], wtv[10];
    if (act) {
        const long ibase = ((long)b * NMBON) * NKC + q * 4;
        const long obase = ((long)b) * (NMBON * NKC) + q * 4;  // t=0 slice
#pragma unroll
        for (int mm = 0; mm < 10; ++mm) {
            const int m = m_base + mm;
            float4 w  = *(const float4*)(W_kc0 + ibase + (long)m * NKC);
            float4 wt = *(const float4*)(wt0   + ibase + (long)m * NKC);
            Wv[mm] = w; wtv[mm] = wt;
            *(float4*)(out_W  + obase + (long)m * NKC) = w;
            *(float4*)(out_wt + obase + (long)m * NKC) = wt;
        }
    } else {
#pragma unroll
        for (int mm = 0; mm < 10; ++mm) {
            Wv[mm]  = make_float4(0.f, 0.f, 0.f, 0.f);
            wtv[mm] = make_float4(0.f, 0.f, 0.f, 0.f);
        }
    }
    __syncthreads();

    // ---------------- time loop ----------------
    int pcur = 0;   // rkc ring index for step t
    for (int t = 0; t < NSTEP; ++t) {
        const int pnext = (pcur == 2) ? 0 : pcur + 1;
        const int hb = t & 1;          // rbkc/ifbn/r double-buffer phase

        float e0 = 0.f, e1 = 0.f;
        // ---- prefetch: issue cp.async for rkc(t+1) into ring[pnext] ----
        // (per-thread ops only — safe in divergent warps)
        if (is_stage) {
            const float* gsrc = rkc_g + (long)(t + 1) * NKC;
            {
                uint32_t dst = (uint32_t)__cvta_generic_to_shared(rkc3 + pnext * 800 + c1 * 4);
                asm volatile("cp.async.cg.shared.global [%0], [%1], 16;\n"
                             :: "r"(dst), "l"(gsrc + c1 * 4));
            }
            if (s < 88) {
                uint32_t dst = (uint32_t)__cvta_generic_to_shared(rkc3 + pnext * 800 + c2 * 4);
                asm volatile("cp.async.cg.shared.global [%0], [%1], 16;\n"
                             :: "r"(dst), "l"(gsrc + c2 * 4));
            }
            asm volatile("cp.async.commit_group;\n" ::: "memory");
            if (s < NFBN) {
                e0 = r_ext[((long)b * 2 + 0) * TT + (t + 1)];
                e1 = r_ext[((long)b * 2 + 1) * TT + (t + 1)];
            }
        }

        // ---- Phase B: I_mbon partials — ALL threads (full-mask shuffles) ----
        {
            float4 kc = make_float4(0.f, 0.f, 0.f, 0.f);
            if (act) kc = *(const float4*)(rkc3 + pcur * 800 + q * 4);
#pragma unroll
            for (int mm = 0; mm < 10; ++mm) {
                float4 w = Wv[mm];     // zero for staging threads
                float p = w.x * kc.x + w.y * kc.y + w.z * kc.z + w.w * kc.w;
                p += __shfl_xor_sync(0xffffffffu, p, 16);
                p += __shfl_xor_sync(0xffffffffu, p, 8);
                p += __shfl_xor_sync(0xffffffffu, p, 4);
                if (lane < 4)
                    red_s[(wig * 4 + lane) * NMBON + (m_base + mm)] = p;
            }
        }
        __syncthreads();   // bar1: red_s ready

        // ---- Phase C (threads 0..99) ∥ staging (rbkc, ifbn, cp.async wait) ----
        const float* rc = r_s + hb * NREC;
        float* rn_buf   = r_s + (hb ^ 1) * NREC;
        if (tid < NREC) {
            const int i = tid;
            float itot;
            if (i < NMBON) {
                float s0 = 0.f, s1 = 0.f, s2 = 0.f, s3 = 0.f;
#pragma unroll
                for (int k = 0; k < 32; k += 4) {
                    s0 += red_s[(k + 0) * NMBON + i];
                    s1 += red_s[(k + 1) * NMBON + i];
                    s2 += red_s[(k + 2) * NMBON + i];
                    s3 += red_s[(k + 3) * NMBON + i];
                }
                itot = (s0 + s1) + (s2 + s3);
            } else if (i < NMBON + NFBN) {
                itot = ifbn[hb * 64 + (i - NMBON)];
            } else {
                itot = 0.f;
            }
            float a0 = 0.f, a1 = 0.f, a2 = 0.f, a3 = 0.f;
#pragma unroll
            for (int j = 0; j < NREC; j += 4) {
                a0 = fmaf(rc[j + 0], WrT[(j + 0) * NREC + i], a0);
                a1 = fmaf(rc[j + 1], WrT[(j + 1) * NREC + i], a1);
                a2 = fmaf(rc[j + 2], WrT[(j + 2) * NREC + i], a2);
                a3 = fmaf(rc[j + 3], WrT[(j + 3) * NREC + i], a3);
            }
            float pre  = ((a0 + a1) + (a2 + a3)) + bias_s[i] + itot;
            float relu = fmaxf(pre, 0.f);
            float rold = rc[i];
            float rn   = fmaf(a_r, relu - rold, rold);
            rn_buf[i] = rn;
            out_r[((long)(t + 1) * BB + b) * NREC + i] = rn;
            if (i >= NREC - NDAN) {
                int m = i - (NREC - NDAN);
                rdan_s[m] = rn;
                float rb = rbdan_s[m];
                rbdan_s[m] = fmaf(a_w, rn - rb, rb);
            }
        } else if (is_stage) {
            // rb_kc(t) = rb_kc(t-1) + a_w*(rkc_t - rb_kc(t-1))
            {
                float4 kc = *(const float4*)(rkc3 + pcur * 800 + c1 * 4);
                float4 bk = *(const float4*)(rbkc + (hb ^ 1) * 800 + c1 * 4);
                bk.x = fmaf(a_w, kc.x - bk.x, bk.x);
                bk.y = fmaf(a_w, kc.y - bk.y, bk.y);
                bk.z = fmaf(a_w, kc.z - bk.z, bk.z);
                bk.w = fmaf(a_w, kc.w - bk.w, bk.w);
                *(float4*)(rbkc + hb * 800 + c1 * 4) = bk;
            }
            if (s < 88) {
                float4 kc = *(const float4*)(rkc3 + pcur * 800 + c2 * 4);
                float4 bk = *(const float4*)(rbkc + (hb ^ 1) * 800 + c2 * 4);
                bk.x = fmaf(a_w, kc.x - bk.x, bk.x);
                bk.y = fmaf(a_w, kc.y - bk.y, bk.y);
                bk.z = fmaf(a_w, kc.z - bk.z, bk.z);
                bk.w = fmaf(a_w, kc.w - bk.w, bk.w);
                *(float4*)(rbkc + hb * 800 + c2 * 4) = bk;
            }
            if (s < NFBN)
                ifbn[(hb ^ 1) * 64 + s] = wext_s[s * 2] * e0 + wext_s[s * 2 + 1] * e1;
            asm volatile("cp.async.wait_group 0;\n" ::: "memory");
        }
        __syncthreads();   // bar2: r_new, rdan/rbdan, rbkc(t), rkc(t+1) ready

        // ---- Phase D: plasticity update + streaming stores ----
        if (act) {
            float4 kc = *(const float4*)(rkc3 + pcur * 800 + q * 4);
            float4 bk = *(const float4*)(rbkc + hb * 800 + q * 4);
            const long obase = ((long)(t + 1) * BB + b) * (NMBON * NKC) + q * 4;
#pragma unroll
            for (int mm = 0; mm < 10; ++mm) {
                const int m = m_base + mm;
                const float rbd = rbdan_s[m];
                const float rd  = rdan_s[m];
                float4 w = Wv[mm], wt = wtv[mm];
                float dw;
                dw = fmaf(rbd, kc.x, -(rd * bk.x)); wt.x = fmaf(dw, dt, wt.x);
                dw = fmaf(rbd, kc.y, -(rd * bk.y)); wt.y = fmaf(dw, dt, wt.y);
                dw = fmaf(rbd, kc.z, -(rd * bk.z)); wt.z = fmaf(dw, dt, wt.z);
                dw = fmaf(rbd, kc.w, -(rd * bk.w)); wt.w = fmaf(dw, dt, wt.w);
                w.x = fminf(fmaxf(fmaf(a_w, wt.x - w.x, w.x), 0.f), W_MAXC);
                w.y = fminf(fmaxf(fmaf(a_w, wt.y - w.y, w.y), 0.f), W_MAXC);
                w.z = fminf(fmaxf(fmaf(a_w, wt.z - w.z, w.z), 0.f), W_MAXC);
                w.w = fminf(fmaxf(fmaf(a_w, wt.w - w.w, w.w), 0.f), W_MAXC);
                Wv[mm] = w; wtv[mm] = wt;
                *(float4*)(out_W  + obase + (long)m * NKC) = w;
                *(float4*)(out_wt + obase + (long)m * NKC) = wt;
            }
        }
        if (warp == 0) {   // readout from r_new (warp 0 is fully act — uniform)
            float v = (lane < NMBON) ? rn_buf[lane] * wro_s[lane] : 0.f;
            v += __shfl_xor_sync(0xffffffffu, v, 16);
            v += __shfl_xor_sync(0xffffffffu, v, 8);
            v += __shfl_xor_sync(0xffffffffu, v, 4);
            v += __shfl_xor_sync(0xffffffffu, v, 2);
            v += __shfl_xor_sync(0xffffffffu, v, 1);
            if (lane == 0) out_ro[(long)(t + 1) * BB + b] = v;
        }
        pcur = pnext;
        // no barrier here: next Phase B writes red_s (last read before bar2 of
        // this step) and reads rkc3[pnext] (staged + bar2) + private registers.
        // The ring slot being prefetched next is 2 steps away from any reader.
    }
}

// ---------------------------------------------------------------------------
extern "C" void kernel_launch(void* const* d_in, const int* in_sizes, int n_in,
                              void* d_out, int out_size) {
    const float* r_kc      = (const float*)d_in[0];
    const float* r_ext     = (const float*)d_in[1];
    const float* time_arr  = (const float*)d_in[2];
    const float* W_kc0     = (const float*)d_in[3];
    const float* wt0       = (const float*)d_in[4];
    const float* W_recur   = (const float*)d_in[5];
    const float* W_readout = (const float*)d_in[6];
    const float* bias      = (const float*)d_in[7];
    const float* W_ext     = (const float*)d_in[8];
    float* out = (float*)d_out;

    cudaFuncSetAttribute(rnn_kernel, cudaFuncAttributeMaxDynamicSharedMemorySize,
                         SM_FLOATS * (int)sizeof(float));

    transpose_kernel<<<dim3(4, 25, BB), dim3(32, 32)>>>(r_kc);
    rnn_kernel<<<BB, NTHREADS, SM_FLOATS * (int)sizeof(float)>>>(
        r_ext, time_arr, W_kc0, wt0, W_recur, W_readout, bias, W_ext, out);
}

// round 4
// speedup vs baseline: 1.4840x; 1.2752x over previous
#include <cuda_runtime.h>
#include <cstdint>

// Problem constants (fixed by setup_inputs)
#define BB      48
#define NKC     800
#define NMBON   20
#define NFBN    60
#define NDAN    20
#define NREC    100
#define TT      121
#define NSTEP   120
#define W_MAXC  0.05f

#define NTHREADS 256
#define NCTA     (BB * 2)

// scratch: r_kc transposed to [B, T, NKC]
__device__ float g_rkcT[(long)BB * TT * NKC];

// ---------------------------------------------------------------------------
// Transpose r_kc [B, NKC, T] -> g_rkcT [B, T, NKC]
// ---------------------------------------------------------------------------
__global__ void transpose_kernel(const float* __restrict__ rkc) {
    __shared__ float tile[32][33];
    const int bz = blockIdx.z;
    const int kt = blockIdx.y;
    const int tt = blockIdx.x;
    const int tx = threadIdx.x, ty = threadIdx.y;

    int k = kt * 32 + ty;
    int t = tt * 32 + tx;
    if (t < TT)
        tile[ty][tx] = rkc[((long)bz * NKC + k) * TT + t];
    __syncthreads();
    int t2 = tt * 32 + ty;
    int k2 = kt * 32 + tx;
    if (t2 < TT)
        g_rkcT[((long)bz * TT + t2) * NKC + k2] = tile[tx][ty];
}

// ---------------------------------------------------------------------------
// Main RNN kernel: cluster of 2 CTAs per batch element (m-split).
//   b = blockIdx.x>>1, rank = blockIdx.x&1, m_off = rank*10.
//   256 threads: q=tid; owners q<200 hold W[m_off+mm][4q..4q+3] mm=0..9 in regs.
//   Staging threads 200..255 prefetch rkc (cp.async ring) + rb_kc + ifbn.
//   Sender threads 128..137 ship 10 local I_mbon floats to peer via DSMEM
//   + mbarrier (count=10, double buffered). Phase C replicated in both CTAs.
// ---------------------------------------------------------------------------
// shared layout (floats), mbar area first (8B aligned):
//  mbar 4 | imb 40 | WrT 10000 | rkc3 2400 | rbkc2 1600 | r 200 | bias 100 |
//  ifbn 128 | red 32*10=320 | rdan 20 | rbdan 20 | wro 20 | wext 120
#define SM_FLOATS (4 + 40 + 10000 + 2400 + 1600 + 200 + 100 + 128 + 320 + 20 + 20 + 20 + 120)

__global__ __launch_bounds__(NTHREADS, 1) __cluster_dims__(2, 1, 1)
void rnn_kernel(
    const float* __restrict__ r_ext,     // [B, 2, T]
    const float* __restrict__ time_arr,  // [T]
    const float* __restrict__ W_kc0,     // [B, 20, 800]
    const float* __restrict__ wt0,       // [B, 20, 800]
    const float* __restrict__ W_recur,   // [100, 100]
    const float* __restrict__ W_readout, // [1, 20]
    const float* __restrict__ bias,      // [100]
    const float* __restrict__ W_ext,     // [60, 2]
    float* __restrict__ out)
{
    extern __shared__ float sm[];
    float* mbar_f  = sm;                  // 4  (2 x u64 mbarriers)
    float* imb     = sm + 4;              // 2 x 20 (exchange buffers)
    float* WrT     = imb + 40;            // 10000
    float* rkc3    = WrT + 10000;         // 3 x 800 (ring)
    float* rbkc    = rkc3 + 2400;         // 2 x 800
    float* r_s     = rbkc + 1600;         // 2 x 100
    float* bias_s  = r_s + 200;           // 100
    float* ifbn    = bias_s + 100;        // 2 x 64
    float* red_s   = ifbn + 128;          // 32 x 10  [slot][mm]
    float* rdan_s  = red_s + 320;         // 20
    float* rbdan_s = rdan_s + 20;         // 20
    float* wro_s   = rbdan_s + 20;        // 20
    float* wext_s  = wro_s + 20;          // 120

    const int tid  = threadIdx.x;
    const int bx   = blockIdx.x;
    const int b    = bx >> 1;
    const int rank = bx & 1;
    const int prank = rank ^ 1;
    const int m_off = rank * 10;
    const int lane = tid & 31;
    const int warp = tid >> 5;
    const int q    = tid;                 // chunk id
    const bool act = (q < 200);

    // staging threads 200..255 (56 threads)
    const bool is_stage = (tid >= 200);
    const int  s = tid - 200;             // 0..55
    // sender threads 128..137
    const bool is_send = (tid >= 128 && tid < 138);
    const int  send_mm = tid - 128;

    float* out_r  = out;
    float* out_W  = out + (long)TT * BB * NREC;
    float* out_wt = out_W + (long)TT * BB * NMBON * NKC;
    float* out_ro = out_wt + (long)TT * BB * NMBON * NKC;

    const float dt  = time_arr[1] - time_arr[0];
    const float a_r = dt;                 // dt / TAU_R
    const float a_w = dt * 0.2f;          // dt / TAU_W

    const float* rkc_g = g_rkcT + (long)b * TT * NKC;

    // cluster-remote addresses (peer's imb / mbar)
    const uint32_t imb_loc  = (uint32_t)__cvta_generic_to_shared(imb);
    const uint32_t mbar_loc = (uint32_t)__cvta_generic_to_shared(mbar_f);
    uint32_t imb_rem, mbar_rem;
    asm("mapa.shared::cluster.u32 %0, %1, %2;" : "=r"(imb_rem)  : "r"(imb_loc),  "r"(prank));
    asm("mapa.shared::cluster.u32 %0, %1, %2;" : "=r"(mbar_rem) : "r"(mbar_loc), "r"(prank));

    // ---------------- init ----------------
    if (tid == 0) {
        asm volatile("mbarrier.init.shared.b64 [%0], 10;" :: "r"(mbar_loc)     : "memory");
        asm volatile("mbarrier.init.shared.b64 [%0], 10;" :: "r"(mbar_loc + 8) : "memory");
    }
    for (int idx = tid; idx < NREC * NREC; idx += NTHREADS) {
        int i = idx / NREC, j = idx % NREC;
        float v = W_recur[idx];
        if (i < NMBON && j >= NREC - NDAN) v = 0.f;
        WrT[j * NREC + i] = v;
    }
    if (tid < NREC)     bias_s[tid] = bias[tid];
    if (tid < NMBON)    wro_s[tid]  = W_readout[tid];
    if (tid >= 32 && tid < 32 + NFBN * 2) wext_s[tid - 32] = W_ext[tid - 32];
    if (tid < NREC) {
        float r0 = (tid < NMBON) ? 0.f : 0.1f;
        r_s[tid] = r0;
        if (rank == 0) out_r[(long)b * NREC + tid] = r0;
    }
    if (tid < NDAN) rbdan_s[tid] = 0.1f;
    for (int k = tid; k < NKC; k += NTHREADS) {
        float v = rkc_g[k];
        rkc3[k] = v;
        rbkc[800 + k] = v;
    }
    __syncthreads();   // wext_s ready before ifbn init below
    if (tid < NFBN) {
        float e0 = r_ext[((long)b * 2 + 0) * TT];
        float e1 = r_ext[((long)b * 2 + 1) * TT];
        ifbn[tid] = wext_s[tid * 2] * e0 + wext_s[tid * 2 + 1] * e1;
    }
    if (tid == 0 && rank == 0) out_ro[b] = 0.f;

    float4 Wv[10], wtv[10];
    if (act) {
        const long ibase = ((long)b * NMBON + m_off) * NKC + q * 4;
        const long obase = ((long)b) * (NMBON * NKC) + (long)m_off * NKC + q * 4;
#pragma unroll
        for (int mm = 0; mm < 10; ++mm) {
            float4 w  = *(const float4*)(W_kc0 + ibase + (long)mm * NKC);
            float4 wt = *(const float4*)(wt0   + ibase + (long)mm * NKC);
            Wv[mm] = w; wtv[mm] = wt;
            *(float4*)(out_W  + obase + (long)mm * NKC) = w;
            *(float4*)(out_wt + obase + (long)mm * NKC) = wt;
        }
    } else {
#pragma unroll
        for (int mm = 0; mm < 10; ++mm) {
            Wv[mm]  = make_float4(0.f, 0.f, 0.f, 0.f);
            wtv[mm] = make_float4(0.f, 0.f, 0.f, 0.f);
        }
    }
    __syncthreads();
    // cluster sync: peer mbarriers initialized before any cross-CTA arrive
    asm volatile("barrier.cluster.arrive.aligned;" ::: "memory");
    asm volatile("barrier.cluster.wait.aligned;"   ::: "memory");

    // ---------------- time loop ----------------
    int pcur = 0;
    for (int t = 0; t < NSTEP; ++t) {
        const int pnext = (pcur == 2) ? 0 : pcur + 1;
        const int hb  = t & 1;
        const int par = (t >> 1) & 1;    // mbarrier phase parity for buffer hb

        float e0 = 0.f, e1 = 0.f;
        // ---- prefetch rkc(t+1) into ring[pnext] (staging threads) ----
        if (is_stage) {
            const float* gsrc = rkc_g + (long)(t + 1) * NKC;
#pragma unroll
            for (int j = 0; j < 4; ++j) {
                int c = s + 56 * j;
                if (c < 200) {
                    uint32_t dst = (uint32_t)__cvta_generic_to_shared(rkc3 + pnext * 800 + c * 4);
                    asm volatile("cp.async.cg.shared.global [%0], [%1], 16;\n"
                                 :: "r"(dst), "l"(gsrc + c * 4));
                }
            }
            asm volatile("cp.async.commit_group;\n" ::: "memory");
            e0 = r_ext[((long)b * 2 + 0) * TT + (t + 1)];
            e1 = r_ext[((long)b * 2 + 1) * TT + (t + 1)];
        }

        // ---- Phase B: I_mbon partials — ALL threads (full-mask shuffles) ----
        {
            float4 kc = make_float4(0.f, 0.f, 0.f, 0.f);
            if (act) kc = *(const float4*)(rkc3 + pcur * 800 + q * 4);
#pragma unroll
            for (int mm = 0; mm < 10; ++mm) {
                float4 w = Wv[mm];   // zero for staging threads
                float p = w.x * kc.x + w.y * kc.y + w.z * kc.z + w.w * kc.w;
                p += __shfl_xor_sync(0xffffffffu, p, 16);
                p += __shfl_xor_sync(0xffffffffu, p, 8);
                p += __shfl_xor_sync(0xffffffffu, p, 4);
                if (lane < 4)
                    red_s[(warp * 4 + lane) * 10 + mm] = p;
            }
        }
        __syncthreads();   // bar1: red_s ready

        // ---- Phase C (0..99) ∥ senders (128..137) ∥ staging (200..255) ----
        const float* rc = r_s + hb * NREC;
        float* rn_buf   = r_s + (hb ^ 1) * NREC;
        if (tid < NREC) {
            const int i = tid;
            float itot;
            if (i < NMBON) {
                const int li = i - m_off;
                if (li >= 0 && li < 10) {
                    // local half: sum 32 slots from red_s
                    float s0 = 0.f, s1 = 0.f, s2 = 0.f, s3 = 0.f;
#pragma unroll
                    for (int k = 0; k < 32; k += 4) {
                        s0 += red_s[(k + 0) * 10 + li];
                        s1 += red_s[(k + 1) * 10 + li];
                        s2 += red_s[(k + 2) * 10 + li];
                        s3 += red_s[(k + 3) * 10 + li];
                    }
                    itot = (s0 + s1) + (s2 + s3);
                } else {
                    // peer half: wait peer's arrival then read DSMEM-delivered value
                    uint32_t done;
                    asm volatile(
                        "{\n\t.reg .pred p;\n\t"
                        "mbarrier.try_wait.parity.acquire.cluster.shared::cta.b64 p, [%1], %2;\n\t"
                        "selp.b32 %0, 1, 0, p;\n\t}"
                        : "=r"(done) : "r"(mbar_loc + hb * 8), "r"(par) : "memory");
                    while (!done) {
                        asm volatile(
                            "{\n\t.reg .pred p;\n\t"
                            "mbarrier.try_wait.parity.acquire.cluster.shared::cta.b64 p, [%1], %2, 0x989680;\n\t"
                            "selp.b32 %0, 1, 0, p;\n\t}"
                            : "=r"(done) : "r"(mbar_loc + hb * 8), "r"(par) : "memory");
                    }
                    itot = imb[hb * 20 + i];
                }
            } else if (i < NMBON + NFBN) {
                itot = ifbn[hb * 64 + (i - NMBON)];
            } else {
                itot = 0.f;
            }
            float a0 = 0.f, a1 = 0.f, a2 = 0.f, a3 = 0.f;
#pragma unroll
            for (int j = 0; j < NREC; j += 4) {
                a0 = fmaf(rc[j + 0], WrT[(j + 0) * NREC + i], a0);
                a1 = fmaf(rc[j + 1], WrT[(j + 1) * NREC + i], a1);
                a2 = fmaf(rc[j + 2], WrT[(j + 2) * NREC + i], a2);
                a3 = fmaf(rc[j + 3], WrT[(j + 3) * NREC + i], a3);
            }
            float pre  = ((a0 + a1) + (a2 + a3)) + bias_s[i] + itot;
            float relu = fmaxf(pre, 0.f);
            float rold = rc[i];
            float rn   = fmaf(a_r, relu - rold, rold);
            rn_buf[i] = rn;
            if (rank == 0) out_r[((long)(t + 1) * BB + b) * NREC + i] = rn;
            if (i >= NREC - NDAN) {
                int m = i - (NREC - NDAN);
                rdan_s[m] = rn;
                float rb = rbdan_s[m];
                rbdan_s[m] = fmaf(a_w, rn - rb, rb);
            }
        } else if (is_send) {
            // compute local I_mbon[send_mm] and push to peer
            const int mm = send_mm;
            float s0 = 0.f, s1 = 0.f, s2 = 0.f, s3 = 0.f;
#pragma unroll
            for (int k = 0; k < 32; k += 4) {
                s0 += red_s[(k + 0) * 10 + mm];
                s1 += red_s[(k + 1) * 10 + mm];
                s2 += red_s[(k + 2) * 10 + mm];
                s3 += red_s[(k + 3) * 10 + mm];
            }
            float v = (s0 + s1) + (s2 + s3);
            // store into peer's imb[hb][m_off+mm], then release-arrive on peer's mbar[hb]
            asm volatile("st.shared::cluster.f32 [%0], %1;"
                         :: "r"(imb_rem + (hb * 20 + m_off + mm) * 4), "f"(v) : "memory");
            asm volatile("mbarrier.arrive.release.cluster.shared::cluster.b64 _, [%0];"
                         :: "r"(mbar_rem + hb * 8) : "memory");
        } else if (is_stage) {
            // rb_kc(t) update + ifbn(t+1) + cp.async wait
#pragma unroll
            for (int j = 0; j < 4; ++j) {
                int c = s + 56 * j;
                if (c < 200) {
                    float4 kc = *(const float4*)(rkc3 + pcur * 800 + c * 4);
                    float4 bk = *(const float4*)(rbkc + (hb ^ 1) * 800 + c * 4);
                    bk.x = fmaf(a_w, kc.x - bk.x, bk.x);
                    bk.y = fmaf(a_w, kc.y - bk.y, bk.y);
                    bk.z = fmaf(a_w, kc.z - bk.z, bk.z);
                    bk.w = fmaf(a_w, kc.w - bk.w, bk.w);
                    *(float4*)(rbkc + hb * 800 + c * 4) = bk;
                }
            }
            if (s < NFBN)
                ifbn[(hb ^ 1) * 64 + s] = wext_s[s * 2] * e0 + wext_s[s * 2 + 1] * e1;
            if (s >= 56 - 4)  // 4 threads cover f = 56..59
            {
                int f = s - (56 - 4) + 56;
                ifbn[(hb ^ 1) * 64 + f] = wext_s[f * 2] * e0 + wext_s[f * 2 + 1] * e1;
            }
            asm volatile("cp.async.wait_group 0;\n" ::: "memory");
        }
        __syncthreads();   // bar2: r_new, rdan/rbdan, rbkc(t), rkc(t+1) ready

        // ---- Phase D: plasticity update + streaming stores ----
        if (act) {
            float4 kc = *(const float4*)(rkc3 + pcur * 800 + q * 4);
            float4 bk = *(const float4*)(rbkc + hb * 800 + q * 4);
            const long obase = ((long)(t + 1) * BB + b) * (NMBON * NKC)
                             + (long)m_off * NKC + q * 4;
#pragma unroll
            for (int mm = 0; mm < 10; ++mm) {
                const float rbd = rbdan_s[m_off + mm];
                const float rd  = rdan_s[m_off + mm];
                float4 w = Wv[mm], wt = wtv[mm];
                float dw;
                dw = fmaf(rbd, kc.x, -(rd * bk.x)); wt.x = fmaf(dw, dt, wt.x);
                dw = fmaf(rbd, kc.y, -(rd * bk.y)); wt.y = fmaf(dw, dt, wt.y);
                dw = fmaf(rbd, kc.z, -(rd * bk.z)); wt.z = fmaf(dw, dt, wt.z);
                dw = fmaf(rbd, kc.w, -(rd * bk.w)); wt.w = fmaf(dw, dt, wt.w);
                w.x = fminf(fmaxf(fmaf(a_w, wt.x - w.x, w.x), 0.f), W_MAXC);
                w.y = fminf(fmaxf(fmaf(a_w, wt.y - w.y, w.y), 0.f), W_MAXC);
                w.z = fminf(fmaxf(fmaf(a_w, wt.z - w.z, w.z), 0.f), W_MAXC);
                w.w = fminf(fmaxf(fmaf(a_w, wt.w - w.w, w.w), 0.f), W_MAXC);
                Wv[mm] = w; wtv[mm] = wt;
                *(float4*)(out_W  + obase + (long)mm * NKC) = w;
                *(float4*)(out_wt + obase + (long)mm * NKC) = wt;
            }
        }
        if (warp == 0 && rank == 0) {   // readout from r_new
            float v = (lane < NMBON) ? rn_buf[lane] * wro_s[lane] : 0.f;
            v += __shfl_xor_sync(0xffffffffu, v, 16);
            v += __shfl_xor_sync(0xffffffffu, v, 8);
            v += __shfl_xor_sync(0xffffffffu, v, 4);
            v += __shfl_xor_sync(0xffffffffu, v, 2);
            v += __shfl_xor_sync(0xffffffffu, v, 1);
            if (lane == 0) out_ro[(long)(t + 1) * BB + b] = v;
        }
        pcur = pnext;
    }

    // keep both CTAs alive until all cross-CTA traffic is done
    asm volatile("barrier.cluster.arrive.aligned;" ::: "memory");
    asm volatile("barrier.cluster.wait.aligned;"   ::: "memory");
}

// ---------------------------------------------------------------------------
extern "C" void kernel_launch(void* const* d_in, const int* in_sizes, int n_in,
                              void* d_out, int out_size) {
    const float* r_kc      = (const float*)d_in[0];
    const float* r_ext     = (const float*)d_in[1];
    const float* time_arr  = (const float*)d_in[2];
    const float* W_kc0     = (const float*)d_in[3];
    const float* wt0       = (const float*)d_in[4];
    const float* W_recur   = (const float*)d_in[5];
    const float* W_readout = (const float*)d_in[6];
    const float* bias      = (const float*)d_in[7];
    const float* W_ext     = (const float*)d_in[8];
    float* out = (float*)d_out;

    cudaFuncSetAttribute(rnn_kernel, cudaFuncAttributeMaxDynamicSharedMemorySize,
                         SM_FLOATS * (int)sizeof(float));

    transpose_kernel<<<dim3(4, 25, BB), dim3(32, 32)>>>(r_kc);
    rnn_kernel<<<NCTA, NTHREADS, SM_FLOATS * (int)sizeof(float)>>>(
        r_ext, time_arr, W_kc0, wt0, W_recur, W_readout, bias, W_ext, out);
}

// round 5
// speedup vs baseline: 1.5707x; 1.0584x over previous
#include <cuda_runtime.h>
#include <cstdint>

// Problem constants (fixed by setup_inputs)
#define BB      48
#define NKC     800
#define NMBON   20
#define NFBN    60
#define NDAN    20
#define NREC    100
#define TT      121
#define NSTEP   120
#define W_MAXC  0.05f
#define WSTR    112     // WrT row stride (j-major), 112 => odd/even lane bank sets disjoint

#define NTHREADS 256
#define NCTA     (BB * 2)

// scratch: r_kc transposed to [B, T, NKC]
__device__ float g_rkcT[(long)BB * TT * NKC];

// ---------------------------------------------------------------------------
// Transpose r_kc [B, NKC, T] -> g_rkcT [B, T, NKC]
// ---------------------------------------------------------------------------
__global__ void transpose_kernel(const float* __restrict__ rkc) {
    __shared__ float tile[32][33];
    const int bz = blockIdx.z;
    const int kt = blockIdx.y;
    const int tt = blockIdx.x;
    const int tx = threadIdx.x, ty = threadIdx.y;

    int k = kt * 32 + ty;
    int t = tt * 32 + tx;
    if (t < TT)
        tile[ty][tx] = rkc[((long)bz * NKC + k) * TT + t];
    __syncthreads();
    int t2 = tt * 32 + ty;
    int k2 = kt * 32 + tx;
    if (t2 < TT)
        g_rkcT[((long)bz * TT + t2) * NKC + k2] = tile[tx][ty];
}

// ---------------------------------------------------------------------------
// Main RNN kernel: cluster of 2 CTAs per batch element (m-split).
//   Phase C matvec parallelized over 200 threads: pair (2i,2i+1) splits the
//   j-dimension by parity, combined with one shfl_xor(1). itot applied late
//   to hide the DSMEM exchange. Senders live in warp 7 (pure staging warp).
// ---------------------------------------------------------------------------
// shared layout (floats):
//  mbar 4 | imb 40 | WrT 100*112 | rkc3 2400 | rbkc2 1600 | r 200 | bias 100 |
//  ifbn 128 | red 32*10=320 | rdan 20 | rbdan 20 | wro 20 | wext 120
#define SM_FLOATS (4 + 40 + 100*WSTR + 2400 + 1600 + 200 + 100 + 128 + 320 + 20 + 20 + 20 + 120)

__global__ __launch_bounds__(NTHREADS, 1) __cluster_dims__(2, 1, 1)
void rnn_kernel(
    const float* __restrict__ r_ext,     // [B, 2, T]
    const float* __restrict__ time_arr,  // [T]
    const float* __restrict__ W_kc0,     // [B, 20, 800]
    const float* __restrict__ wt0,       // [B, 20, 800]
    const float* __restrict__ W_recur,   // [100, 100]
    const float* __restrict__ W_readout, // [1, 20]
    const float* __restrict__ bias,      // [100]
    const float* __restrict__ W_ext,     // [60, 2]
    float* __restrict__ out)
{
    extern __shared__ float sm[];
    float* mbar_f  = sm;                  // 4  (2 x u64 mbarriers)
    float* imb     = sm + 4;              // 2 x 20 (exchange buffers)
    float* WrT     = imb + 40;            // 100 x WSTR, WrT[j*WSTR + i]
    float* rkc3    = WrT + 100 * WSTR;    // 3 x 800 (ring)
    float* rbkc    = rkc3 + 2400;         // 2 x 800
    float* r_s     = rbkc + 1600;         // 2 x 100
    float* bias_s  = r_s + 200;           // 100
    float* ifbn    = bias_s + 100;        // 2 x 64
    float* red_s   = ifbn + 128;          // 32 x 10  [slot][mm]
    float* rdan_s  = red_s + 320;         // 20
    float* rbdan_s = rdan_s + 20;         // 20
    float* wro_s   = rbdan_s + 20;        // 20
    float* wext_s  = wro_s + 20;          // 120

    const int tid  = threadIdx.x;
    const int bx   = blockIdx.x;
    const int b    = bx >> 1;
    const int rank = bx & 1;
    const int prank = rank ^ 1;
    const int m_off = rank * 10;
    const int lane = tid & 31;
    const int warp = tid >> 5;
    const int q    = tid;
    const bool act = (q < 200);

    // staging threads 200..255 (56 threads)
    const bool is_stage = (tid >= 200);
    const int  s = tid - 200;             // 0..55
    // sender threads: warp 7 lanes 0..9 (tid 224..233) — pure staging warp
    const bool is_send = (tid >= 224 && tid < 234);
    const int  send_mm = tid - 224;

    float* out_r  = out;
    float* out_W  = out + (long)TT * BB * NREC;
    float* out_wt = out_W + (long)TT * BB * NMBON * NKC;
    float* out_ro = out_wt + (long)TT * BB * NMBON * NKC;

    const float dt  = time_arr[1] - time_arr[0];
    const float a_r = dt;                 // dt / TAU_R
    const float a_w = dt * 0.2f;          // dt / TAU_W

    const float* rkc_g = g_rkcT + (long)b * TT * NKC;

    // cluster-remote addresses (peer's imb / mbar)
    const uint32_t imb_loc  = (uint32_t)__cvta_generic_to_shared(imb);
    const uint32_t mbar_loc = (uint32_t)__cvta_generic_to_shared(mbar_f);
    uint32_t imb_rem, mbar_rem;
    asm("mapa.shared::cluster.u32 %0, %1, %2;" : "=r"(imb_rem)  : "r"(imb_loc),  "r"(prank));
    asm("mapa.shared::cluster.u32 %0, %1, %2;" : "=r"(mbar_rem) : "r"(mbar_loc), "r"(prank));

    // ---------------- init ----------------
    if (tid == 0) {
        asm volatile("mbarrier.init.shared.b64 [%0], 10;" :: "r"(mbar_loc)     : "memory");
        asm volatile("mbarrier.init.shared.b64 [%0], 10;" :: "r"(mbar_loc + 8) : "memory");
    }
    for (int idx = tid; idx < NREC * NREC; idx += NTHREADS) {
        int i = idx / NREC, j = idx % NREC;
        float v = W_recur[idx];
        if (i < NMBON && j >= NREC - NDAN) v = 0.f;
        WrT[j * WSTR + i] = v;
    }
    if (tid < NREC)     bias_s[tid] = bias[tid];
    if (tid < NMBON)    wro_s[tid]  = W_readout[tid];
    if (tid >= 32 && tid < 32 + NFBN * 2) wext_s[tid - 32] = W_ext[tid - 32];
    if (tid < NREC) {
        float r0 = (tid < NMBON) ? 0.f : 0.1f;
        r_s[tid] = r0;
        if (rank == 0) out_r[(long)b * NREC + tid] = r0;
    }
    if (tid < NDAN) rbdan_s[tid] = 0.1f;
    for (int k = tid; k < NKC; k += NTHREADS) {
        float v = rkc_g[k];
        rkc3[k] = v;
        rbkc[800 + k] = v;
    }
    __syncthreads();   // wext_s ready before ifbn init below
    if (tid < NFBN) {
        float e0 = r_ext[((long)b * 2 + 0) * TT];
        float e1 = r_ext[((long)b * 2 + 1) * TT];
        ifbn[tid] = wext_s[tid * 2] * e0 + wext_s[tid * 2 + 1] * e1;
    }
    if (tid == 0 && rank == 0) out_ro[b] = 0.f;

    float4 Wv[10], wtv[10];
    if (act) {
        const long ibase = ((long)b * NMBON + m_off) * NKC + q * 4;
        const long obase = ((long)b) * (NMBON * NKC) + (long)m_off * NKC + q * 4;
#pragma unroll
        for (int mm = 0; mm < 10; ++mm) {
            float4 w  = *(const float4*)(W_kc0 + ibase + (long)mm * NKC);
            float4 wt = *(const float4*)(wt0   + ibase + (long)mm * NKC);
            Wv[mm] = w; wtv[mm] = wt;
            *(float4*)(out_W  + obase + (long)mm * NKC) = w;
            *(float4*)(out_wt + obase + (long)mm * NKC) = wt;
        }
    } else {
#pragma unroll
        for (int mm = 0; mm < 10; ++mm) {
            Wv[mm]  = make_float4(0.f, 0.f, 0.f, 0.f);
            wtv[mm] = make_float4(0.f, 0.f, 0.f, 0.f);
        }
    }
    __syncthreads();
    asm volatile("barrier.cluster.arrive.aligned;" ::: "memory");
    asm volatile("barrier.cluster.wait.aligned;"   ::: "memory");

    // ---------------- time loop ----------------
    int pcur = 0;
    for (int t = 0; t < NSTEP; ++t) {
        const int pnext = (pcur == 2) ? 0 : pcur + 1;
        const int hb  = t & 1;
        const int par = (t >> 1) & 1;

        float e0 = 0.f, e1 = 0.f;
        // ---- prefetch rkc(t+1) into ring[pnext] (staging threads) ----
        if (is_stage) {
            const float* gsrc = rkc_g + (long)(t + 1) * NKC;
#pragma unroll
            for (int j = 0; j < 4; ++j) {
                int c = s + 56 * j;
                if (c < 200) {
                    uint32_t dst = (uint32_t)__cvta_generic_to_shared(rkc3 + pnext * 800 + c * 4);
                    asm volatile("cp.async.cg.shared.global [%0], [%1], 16;\n"
                                 :: "r"(dst), "l"(gsrc + c * 4));
                }
            }
            asm volatile("cp.async.commit_group;\n" ::: "memory");
            e0 = r_ext[((long)b * 2 + 0) * TT + (t + 1)];
            e1 = r_ext[((long)b * 2 + 1) * TT + (t + 1)];
        }

        // ---- Phase B: I_mbon partials — ALL threads (full-mask shuffles) ----
        {
            float4 kc = make_float4(0.f, 0.f, 0.f, 0.f);
            if (act) kc = *(const float4*)(rkc3 + pcur * 800 + q * 4);
#pragma unroll
            for (int mm = 0; mm < 10; ++mm) {
                float4 w = Wv[mm];   // zero for staging threads
                float p = w.x * kc.x + w.y * kc.y + w.z * kc.z + w.w * kc.w;
                p += __shfl_xor_sync(0xffffffffu, p, 16);
                p += __shfl_xor_sync(0xffffffffu, p, 8);
                p += __shfl_xor_sync(0xffffffffu, p, 4);
                if (lane < 4)
                    red_s[(warp * 4 + lane) * 10 + mm] = p;
            }
        }
        __syncthreads();   // bar1: red_s ready

        // ---- Phase C (0..199, pair-split matvec) ∥ stage/senders (200..255) ----
        const float* rc = r_s + hb * NREC;
        float* rn_buf   = r_s + (hb ^ 1) * NREC;
        if (tid < 200) {
            const int i = tid >> 1;
            const int h = tid & 1;
            const float* wcol = WrT + h * WSTR + i;   // j offsets become immediates
            const float* rch  = rc + h;
            float a0 = 0.f, a1 = 0.f, a2 = 0.f, a3 = 0.f;
#pragma unroll
            for (int bq = 0; bq < 25; ++bq) {
                if (bq & 1) {
                    a2 = fmaf(rch[4 * bq],     wcol[(4 * bq)     * WSTR], a2);
                    a3 = fmaf(rch[4 * bq + 2], wcol[(4 * bq + 2) * WSTR], a3);
                } else {
                    a0 = fmaf(rch[4 * bq],     wcol[(4 * bq)     * WSTR], a0);
                    a1 = fmaf(rch[4 * bq + 2], wcol[(4 * bq + 2) * WSTR], a1);
                }
            }
            float p = (a0 + a2) + (a1 + a3);
            const unsigned mvmask = (tid < 192) ? 0xffffffffu : 0x000000ffu;
            p += __shfl_xor_sync(mvmask, p, 1);   // pair combine: both lanes get full dot

            if (h == 0) {
                float itot;
                if (i < NMBON) {
                    const int li = i - m_off;
                    if (li >= 0 && li < 10) {
                        float s0 = 0.f, s1 = 0.f, s2 = 0.f, s3 = 0.f;
#pragma unroll
                        for (int k = 0; k < 32; k += 4) {
                            s0 += red_s[(k + 0) * 10 + li];
                            s1 += red_s[(k + 1) * 10 + li];
                            s2 += red_s[(k + 2) * 10 + li];
                            s3 += red_s[(k + 3) * 10 + li];
                        }
                        itot = (s0 + s1) + (s2 + s3);
                    } else {
                        // peer half — by now the arrive has almost surely landed
                        uint32_t done;
                        asm volatile(
                            "{\n\t.reg .pred p;\n\t"
                            "mbarrier.try_wait.parity.acquire.cluster.shared::cta.b64 p, [%1], %2;\n\t"
                            "selp.b32 %0, 1, 0, p;\n\t}"
                            : "=r"(done) : "r"(mbar_loc + hb * 8), "r"(par) : "memory");
                        while (!done) {
                            asm volatile(
                                "{\n\t.reg .pred p;\n\t"
                                "mbarrier.try_wait.parity.acquire.cluster.shared::cta.b64 p, [%1], %2, 0x989680;\n\t"
                                "selp.b32 %0, 1, 0, p;\n\t}"
                                : "=r"(done) : "r"(mbar_loc + hb * 8), "r"(par) : "memory");
                        }
                        itot = imb[hb * 20 + i];
                    }
                } else if (i < NMBON + NFBN) {
                    itot = ifbn[hb * 64 + (i - NMBON)];
                } else {
                    itot = 0.f;
                }
                float pre  = p + bias_s[i] + itot;
                float relu = fmaxf(pre, 0.f);
                float rold = rc[i];
                float rn   = fmaf(a_r, relu - rold, rold);
                rn_buf[i] = rn;
                if (rank == 0) out_r[((long)(t + 1) * BB + b) * NREC + i] = rn;
                if (i >= NREC - NDAN) {
                    int m = i - (NREC - NDAN);
                    rdan_s[m] = rn;
                    float rb = rbdan_s[m];
                    rbdan_s[m] = fmaf(a_w, rn - rb, rb);
                }
            }
        } else {
            // senders first (warp 7 lanes 0-9): push local I_mbon to peer ASAP
            if (is_send) {
                const int mm = send_mm;
                float s0 = 0.f, s1 = 0.f, s2 = 0.f, s3 = 0.f;
#pragma unroll
                for (int k = 0; k < 32; k += 4) {
                    s0 += red_s[(k + 0) * 10 + mm];
                    s1 += red_s[(k + 1) * 10 + mm];
                    s2 += red_s[(k + 2) * 10 + mm];
                    s3 += red_s[(k + 3) * 10 + mm];
                }
                float v = (s0 + s1) + (s2 + s3);
                asm volatile("st.shared::cluster.f32 [%0], %1;"
                             :: "r"(imb_rem + (hb * 20 + m_off + mm) * 4), "f"(v) : "memory");
                asm volatile("mbarrier.arrive.release.cluster.shared::cluster.b64 _, [%0];"
                             :: "r"(mbar_rem + hb * 8) : "memory");
            }
            // rb_kc(t) update + ifbn(t+1) + cp.async wait
#pragma unroll
            for (int j = 0; j < 4; ++j) {
                int c = s + 56 * j;
                if (c < 200) {
                    float4 kc = *(const float4*)(rkc3 + pcur * 800 + c * 4);
                    float4 bk = *(const float4*)(rbkc + (hb ^ 1) * 800 + c * 4);
                    bk.x = fmaf(a_w, kc.x - bk.x, bk.x);
                    bk.y = fmaf(a_w, kc.y - bk.y, bk.y);
                    bk.z = fmaf(a_w, kc.z - bk.z, bk.z);
                    bk.w = fmaf(a_w, kc.w - bk.w, bk.w);
                    *(float4*)(rbkc + hb * 800 + c * 4) = bk;
                }
            }
            if (s < NFBN)
                ifbn[(hb ^ 1) * 64 + s] = wext_s[s * 2] * e0 + wext_s[s * 2 + 1] * e1;
            if (s >= 56 - 4) {  // 4 threads cover f = 56..59
                int f = s - (56 - 4) + 56;
                ifbn[(hb ^ 1) * 64 + f] = wext_s[f * 2] * e0 + wext_s[f * 2 + 1] * e1;
            }
            asm volatile("cp.async.wait_group 0;\n" ::: "memory");
        }
        __syncthreads();   // bar2: r_new, rdan/rbdan, rbkc(t), rkc(t+1) ready

        // ---- Phase D: plasticity update + streaming stores ----
        if (act) {
            float4 kc = *(const float4*)(rkc3 + pcur * 800 + q * 4);
            float4 bk = *(const float4*)(rbkc + hb * 800 + q * 4);
            const long obase = ((long)(t + 1) * BB + b) * (NMBON * NKC)
                             + (long)m_off * NKC + q * 4;
#pragma unroll
            for (int mm = 0; mm < 10; ++mm) {
                const float rbd = rbdan_s[m_off + mm];
                const float rd  = rdan_s[m_off + mm];
                float4 w = Wv[mm], wt = wtv[mm];
                float dw;
                dw = fmaf(rbd, kc.x, -(rd * bk.x)); wt.x = fmaf(dw, dt, wt.x);
                dw = fmaf(rbd, kc.y, -(rd * bk.y)); wt.y = fmaf(dw, dt, wt.y);
                dw = fmaf(rbd, kc.z, -(rd * bk.z)); wt.z = fmaf(dw, dt, wt.z);
                dw = fmaf(rbd, kc.w, -(rd * bk.w)); wt.w = fmaf(dw, dt, wt.w);
                w.x = fminf(fmaxf(fmaf(a_w, wt.x - w.x, w.x), 0.f), W_MAXC);
                w.y = fminf(fmaxf(fmaf(a_w, wt.y - w.y, w.y), 0.f), W_MAXC);
                w.z = fminf(fmaxf(fmaf(a_w, wt.z - w.z, w.z), 0.f), W_MAXC);
                w.w = fminf(fmaxf(fmaf(a_w, wt.w - w.w, w.w), 0.f), W_MAXC);
                Wv[mm] = w; wtv[mm] = wt;
                *(float4*)(out_W  + obase + (long)mm * NKC) = w;
                *(float4*)(out_wt + obase + (long)mm * NKC) = wt;
            }
        }
        if (warp == 0 && rank == 0) {   // readout from r_new
            float v = (lane < NMBON) ? rn_buf[lane] * wro_s[lane] : 0.f;
            v += __shfl_xor_sync(0xffffffffu, v, 16);
            v += __shfl_xor_sync(0xffffffffu, v, 8);
            v += __shfl_xor_sync(0xffffffffu, v, 4);
            v += __shfl_xor_sync(0xffffffffu, v, 2);
            v += __shfl_xor_sync(0xffffffffu, v, 1);
            if (lane == 0) out_ro[(long)(t + 1) * BB + b] = v;
        }
        pcur = pnext;
    }

    // keep both CTAs alive until all cross-CTA traffic is done
    asm volatile("barrier.cluster.arrive.aligned;" ::: "memory");
    asm volatile("barrier.cluster.wait.aligned;"   ::: "memory");
}

// ---------------------------------------------------------------------------
extern "C" void kernel_launch(void* const* d_in, const int* in_sizes, int n_in,
                              void* d_out, int out_size) {
    const float* r_kc      = (const float*)d_in[0];
    const float* r_ext     = (const float*)d_in[1];
    const float* time_arr  = (const float*)d_in[2];
    const float* W_kc0     = (const float*)d_in[3];
    const float* wt0       = (const float*)d_in[4];
    const float* W_recur   = (const float*)d_in[5];
    const float* W_readout = (const float*)d_in[6];
    const float* bias      = (const float*)d_in[7];
    const float* W_ext     = (const float*)d_in[8];
    float* out = (float*)d_out;

    cudaFuncSetAttribute(rnn_kernel, cudaFuncAttributeMaxDynamicSharedMemorySize,
                         SM_FLOATS * (int)sizeof(float));

    transpose_kernel<<<dim3(4, 25, BB), dim3(32, 32)>>>(r_kc);
    rnn_kernel<<<NCTA, NTHREADS, SM_FLOATS * (int)sizeof(float)>>>(
        r_ext, time_arr, W_kc0, wt0, W_recur, W_readout, bias, W_ext, out);
}